// round 7
// baseline (speedup 1.0000x reference)
#include <cuda_runtime.h>
#include <cstdint>

#define HEADS 8
#define BATCH 8
#define SEQ   1024
#define HID   512
#define DK    64
#define NH    (HEADS*BATCH)   /* 64 */
#define TOPK  51
#define SCALE 1.2f

// ---------------- device scratch (allocation-free) ----------------
__device__ float g_Qt[(size_t)NH * DK * SEQ];      // [n][c][s]
__device__ float g_Kt[(size_t)NH * DK * SEQ];      // [n][c][s]
__device__ float g_V [(size_t)NH * SEQ * DK];      // [n][s][c]
__device__ float g_attn[(size_t)BATCH * SEQ * HID];// [b][s][h*64+c]

// ---------------- cp.async helpers ----------------
__device__ __forceinline__ void cp16(float* dst, const float* src) {
    unsigned u = (unsigned)__cvta_generic_to_shared(dst);
    asm volatile("cp.async.cg.shared.global [%0], [%1], 16;\n" :: "r"(u), "l"(src));
}
__device__ __forceinline__ void cp_commit() { asm volatile("cp.async.commit_group;\n" ::: "memory"); }
__device__ __forceinline__ void cp_wait1()  { asm volatile("cp.async.wait_group 1;\n" ::: "memory"); }
__device__ __forceinline__ void cp_wait0()  { asm volatile("cp.async.wait_group 0;\n" ::: "memory"); }

__device__ __forceinline__ float ex2f(float x) {
    float r; asm("ex2.approx.ftz.f32 %0, %1;" : "=f"(r) : "f"(x)); return r;
}

// =================================================================
// SGEMM: C[8192,512] = X[8192,512] @ W[512,512] + bias  (unchanged, at FFMA roofline)
// mode 0: out[(h*8+b)][c][s]   mode 1: out[(h*8+b)][s][c]   mode 2: out[m][n]
// =================================================================
__global__ void __launch_bounds__(256) sgemm512(
    const float* __restrict__ X, const float* __restrict__ W,
    const float* __restrict__ bias, float* __restrict__ out, int mode)
{
    __shared__ float As[16][68];
    __shared__ float Bs[16][64];

    const int tid = threadIdx.x;
    const int tx = tid & 15, ty = tid >> 4;
    const int bm = blockIdx.y * 64, bn = blockIdx.x * 64;

    const int am = tid >> 2, ak = (tid & 3) << 2;
    const int wk = tid >> 4, wn = (tid & 15) << 2;

    float acc[4][4] = {};

    for (int k0 = 0; k0 < 512; k0 += 16) {
        float4 xa = *(const float4*)&X[(bm + am) * 512 + k0 + ak];
        float4 wb = *(const float4*)&W[(k0 + wk) * 512 + bn + wn];
        __syncthreads();
        As[ak + 0][am] = xa.x; As[ak + 1][am] = xa.y;
        As[ak + 2][am] = xa.z; As[ak + 3][am] = xa.w;
        *(float4*)&Bs[wk][wn] = wb;
        __syncthreads();
#pragma unroll
        for (int kk = 0; kk < 16; kk++) {
            const float4 a4 = *(const float4*)&As[kk][ty * 4];
            const float4 b4 = *(const float4*)&Bs[kk][tx * 4];
            const float a[4] = {a4.x, a4.y, a4.z, a4.w};
            const float b[4] = {b4.x, b4.y, b4.z, b4.w};
#pragma unroll
            for (int i = 0; i < 4; i++)
#pragma unroll
                for (int j = 0; j < 4; j++)
                    acc[i][j] = fmaf(a[i], b[j], acc[i][j]);
        }
    }

    const float4 bb4 = *(const float4*)(bias + bn + tx * 4);
    const float bb[4] = {bb4.x, bb4.y, bb4.z, bb4.w};
    const int m0 = bm + ty * 4;
    const int n0 = bn + tx * 4;

    if (mode == 2) {
#pragma unroll
        for (int i = 0; i < 4; i++) {
            float4 o = make_float4(acc[i][0] + bb[0], acc[i][1] + bb[1],
                                   acc[i][2] + bb[2], acc[i][3] + bb[3]);
            *(float4*)(out + (m0 + i) * 512 + n0) = o;
        }
    } else if (mode == 1) {  // V: [(h*8+b)][s][c]
        const int h = n0 >> 6, c = n0 & 63;
        const int b_ = m0 >> 10, s = m0 & 1023;
        float* base = out + ((h * 8 + b_) * SEQ + s) * DK + c;
#pragma unroll
        for (int i = 0; i < 4; i++) {
            float4 o = make_float4(acc[i][0] + bb[0], acc[i][1] + bb[1],
                                   acc[i][2] + bb[2], acc[i][3] + bb[3]);
            *(float4*)(base + i * DK) = o;
        }
    } else {                 // Q/K transposed: [(h*8+b)][c][s]
        const int h = n0 >> 6;
        const int b_ = m0 >> 10, s = m0 & 1023;
        float* base = out + (h * 8 + b_) * DK * SEQ + s;
#pragma unroll
        for (int j = 0; j < 4; j++) {
            const int c = (n0 & 63) + j;
            float4 o = make_float4(acc[0][j] + bb[j], acc[1][j] + bb[j],
                                   acc[2][j] + bb[j], acc[3][j] + bb[j]);
            *(float4*)(base + c * SEQ) = o;
        }
    }
}

// =================================================================
// Fused attention, 512 threads (16 warps = 4/SMSP for issue-rate).
// One CTA = 32 queries of one n = h*8+b. Same SMEM layout as R5.
// =================================================================
#define KVBUF 8704                                     /* floats per buffer */
#define ATTN_SMEM_BYTES ((2048 + 32768 + 2*KVBUF) * 4) /* 208896 */

__device__ __forceinline__ void load_k_chunk(float* buf, const float* gK, int kc, int tid) {
#pragma unroll
    for (int j = 0; j < 4; j++) {                     // 2048 float4 / 512 thr
        int f = tid + 512 * j;
        int c = f >> 5;
        int kk = (f & 31) << 2;
        cp16(buf + c * 128 + kk, gK + c * SEQ + kc * 128 + kk);
    }
}
__device__ __forceinline__ void load_v_chunk(float* buf, const float* gV, int kc, int tid) {
#pragma unroll
    for (int j = 0; j < 4; j++) {
        int f = tid + 512 * j;
        int key = f >> 4;
        int c4 = (f & 15) << 2;
        cp16(buf + key * 68 + c4, gV + (kc * 128 + key) * DK + c4);
    }
}

__global__ void __launch_bounds__(512, 1) attn_kernel(const int* __restrict__ randidx, int n_rand)
{
    extern __shared__ float sm[];
    float* sQt  = sm;                    // [64][32]
    float* sS   = sm + 2048;             // [32][1024]
    float* sKV0 = sm + 2048 + 32768;
    float* sKV1 = sKV0 + KVBUF;
    __shared__ unsigned sRand[32];

    const int tid  = threadIdx.x;
    const int lane = tid & 31;
    const int warp = tid >> 5;           // 0..15
    const int qb = blockIdx.x;           // 0..31
    const int n  = blockIdx.y;           // h*8 + b

    const float* gQ = g_Qt + n * (DK * SEQ);
    const float* gK = g_Kt + n * (DK * SEQ);
    const float* gV = g_V  + n * (SEQ * DK);

    load_k_chunk(sKV0, gK, 0, tid);      // kick off K chunk 0
    cp_commit();

    if (tid < 32) sRand[tid] = 0u;
    {   // Q tile (pre-scaled by 1/sqrt(64)): 512 float4, one per thread
        int c = tid >> 3, s4 = (tid & 7) << 2;
        float4 v = *(const float4*)(gQ + c * SEQ + qb * 32 + s4);
        v.x *= 0.125f; v.y *= 0.125f; v.z *= 0.125f; v.w *= 0.125f;
        *(float4*)(sQt + c * 32 + s4) = v;
    }
    __syncthreads();
    if (tid < n_rand) {
        int v = randidx[tid] & (SEQ - 1);
        atomicOr(&sRand[v >> 5], 1u << (v & 31));
    }

    // ---------------- scores into sS[32][1024] ----------------
    {
        const int r0 = warp * 2;         // 16 warps x 2 rows = 32
        const int key0 = lane * 4;
        const float* qp = sQt + r0;
        for (int kc = 0; kc < 8; kc++) {
            if (kc < 7) {
                load_k_chunk((kc & 1) ? sKV0 : sKV1, gK, kc + 1, tid);
                cp_commit();
                cp_wait1();
            } else {
                cp_wait0();
            }
            __syncthreads();
            const float* kp = ((kc & 1) ? sKV1 : sKV0) + key0;
            float acc[2][4] = {};
#pragma unroll 16
            for (int c = 0; c < 64; c++) {
                const float2 q  = *(const float2*)(qp + c * 32);
                const float4 k4 = *(const float4*)(kp + c * 128);
                acc[0][0] = fmaf(q.x, k4.x, acc[0][0]);
                acc[0][1] = fmaf(q.x, k4.y, acc[0][1]);
                acc[0][2] = fmaf(q.x, k4.z, acc[0][2]);
                acc[0][3] = fmaf(q.x, k4.w, acc[0][3]);
                acc[1][0] = fmaf(q.y, k4.x, acc[1][0]);
                acc[1][1] = fmaf(q.y, k4.y, acc[1][1]);
                acc[1][2] = fmaf(q.y, k4.z, acc[1][2]);
                acc[1][3] = fmaf(q.y, k4.w, acc[1][3]);
            }
#pragma unroll
            for (int i = 0; i < 2; i++) {
                float4 o = make_float4(acc[i][0], acc[i][1], acc[i][2], acc[i][3]);
                *(float4*)(sS + (r0 + i) * 1024 + kc * 128 + key0) = o;
            }
            __syncthreads();
        }
    }

    load_v_chunk(sKV0, gV, 0, tid);      // prefetch V chunk 0 (overlaps topk)
    cp_commit();

    // ---------- exp + exact top-51 + rand-mask + rescale+renorm ----------
    {
#pragma unroll 1
        for (int rr = 0; rr < 2; rr++) {
            const int r = warp * 2 + rr;
            float* row = sS + r * 1024;
            float e[32];
            float m = -3.0e38f;
#pragma unroll
            for (int i = 0; i < 32; i++) { e[i] = row[lane + 32 * i]; m = fmaxf(m, e[i]); }
#pragma unroll
            for (int off = 16; off; off >>= 1) m = fmaxf(m, __shfl_xor_sync(0xFFFFFFFFu, m, off));
#pragma unroll
            for (int i = 0; i < 32; i++) e[i] = ex2f((e[i] - m) * 1.4426950408889634f);

            // exact 51st-largest via radix bisection on fp32 bits (e>0)
            unsigned prefix = 0u;
#pragma unroll 1
            for (int bit = 29; bit >= 0; bit--) {
                const unsigned cand = prefix | (1u << bit);
                int c = 0;
#pragma unroll
                for (int i = 0; i < 32; i++) c += (__float_as_uint(e[i]) >= cand) ? 1 : 0;
                if (__reduce_add_sync(0xFFFFFFFFu, c) >= TOPK) prefix = cand;
            }

            float s = 0.0f;
#pragma unroll
            for (int i = 0; i < 32; i++) {
                bool sel = (__float_as_uint(e[i]) >= prefix) || ((sRand[i] >> lane) & 1u);
                e[i] = sel ? e[i] * SCALE : e[i];
                s += e[i];
            }
#pragma unroll
            for (int off = 16; off; off >>= 1) s += __shfl_xor_sync(0xFFFFFFFFu, s, off);
            const float inv = 1.0f / s;
#pragma unroll
            for (int i = 0; i < 32; i++) row[lane + 32 * i] = e[i] * inv;
        }
    }

    // ---------------- AV: out[32 q][64 c] ----------------
    {
        const int r0 = warp * 2;
        const int c0 = lane * 2;
        float a00 = 0.f, a01 = 0.f, a10 = 0.f, a11 = 0.f;
        const float* s0 = sS + r0 * 1024;
        const float* s1 = s0 + 1024;
        for (int kc = 0; kc < 8; kc++) {
            if (kc < 7) {
                load_v_chunk((kc & 1) ? sKV0 : sKV1, gV, kc + 1, tid);
                cp_commit();
                cp_wait1();
            } else {
                cp_wait0();
            }
            __syncthreads();
            const float* Vb = ((kc & 1) ? sKV1 : sKV0) + c0;
            const int o = kc * 128;
#pragma unroll 8
            for (int kk = 0; kk < 128; kk += 4) {
                const float4 t0 = *(const float4*)(s0 + o + kk);
                const float4 t1 = *(const float4*)(s1 + o + kk);
                const float a0[4] = {t0.x, t0.y, t0.z, t0.w};
                const float a1[4] = {t1.x, t1.y, t1.z, t1.w};
#pragma unroll
                for (int t = 0; t < 4; t++) {
                    const float2 v2 = *(const float2*)(Vb + (kk + t) * 68);
                    a00 = fmaf(a0[t], v2.x, a00);
                    a01 = fmaf(a0[t], v2.y, a01);
                    a10 = fmaf(a1[t], v2.x, a10);
                    a11 = fmaf(a1[t], v2.y, a11);
                }
            }
            __syncthreads();
        }
        // write to g_attn[b][s][h*64+c]
        const int h = n >> 3, b_ = n & 7;
        const int s = qb * 32 + r0;
        float* ob = g_attn + (b_ * SEQ + s) * HID + h * 64 + c0;
        *(float2*)(ob)       = make_float2(a00, a01);
        *(float2*)(ob + HID) = make_float2(a10, a11);
    }
}

// =================================================================
extern "C" void kernel_launch(void* const* d_in, const int* in_sizes, int n_in,
                              void* d_out, int out_size) {
    const float* Qx  = (const float*)d_in[0];
    const float* KVx = (const float*)d_in[1];
    const float* Wq  = (const float*)d_in[2];
    const float* bq  = (const float*)d_in[3];
    const float* Wk  = (const float*)d_in[4];
    const float* bk  = (const float*)d_in[5];
    const float* Wv  = (const float*)d_in[6];
    const float* bv  = (const float*)d_in[7];
    const float* Wo  = (const float*)d_in[8];
    const float* bo  = (const float*)d_in[9];
    const int* ridx  = (const int*)d_in[10];
    const int n_rand = in_sizes[10];
    float* out = (float*)d_out;

    float *pQt, *pKt, *pV, *pA;
    cudaGetSymbolAddress((void**)&pQt, g_Qt);
    cudaGetSymbolAddress((void**)&pKt, g_Kt);
    cudaGetSymbolAddress((void**)&pV,  g_V);
    cudaGetSymbolAddress((void**)&pA,  g_attn);

    cudaFuncSetAttribute(attn_kernel, cudaFuncAttributeMaxDynamicSharedMemorySize, ATTN_SMEM_BYTES);

    dim3 gg(8, 128);   // N tiles (512/64), M tiles (8192/64)
    sgemm512<<<gg, 256>>>(Qx,  Wq, bq, pQt, 0);
    sgemm512<<<gg, 256>>>(KVx, Wk, bk, pKt, 0);
    sgemm512<<<gg, 256>>>(KVx, Wv, bv, pV,  1);
    attn_kernel<<<dim3(32, 64), 512, ATTN_SMEM_BYTES>>>(ridx, n_rand);
    sgemm512<<<gg, 256>>>(pA, Wo, bo, out, 2);
}

// round 9
// speedup vs baseline: 1.1499x; 1.1499x over previous
#include <cuda_runtime.h>
#include <cstdint>

#define HEADS 8
#define BATCH 8
#define SEQ   1024
#define HID   512
#define DK    64
#define NH    (HEADS*BATCH)   /* 64 */
#define TOPK  51
#define SCALE 1.2f

// ---------------- device scratch (allocation-free) ----------------
__device__ float g_Qt[(size_t)NH * DK * SEQ];      // [n][c][s]
__device__ float g_Kt[(size_t)NH * DK * SEQ];      // [n][c][s]
__device__ float g_V [(size_t)NH * SEQ * DK];      // [n][s][c]
__device__ float g_attn[(size_t)BATCH * SEQ * HID];// [b][s][h*64+c]

// ---------------- cp.async helpers ----------------
__device__ __forceinline__ void cp16(float* dst, const float* src) {
    unsigned u = (unsigned)__cvta_generic_to_shared(dst);
    asm volatile("cp.async.cg.shared.global [%0], [%1], 16;\n" :: "r"(u), "l"(src));
}
__device__ __forceinline__ void cp_commit() { asm volatile("cp.async.commit_group;\n" ::: "memory"); }
__device__ __forceinline__ void cp_wait1()  { asm volatile("cp.async.wait_group 1;\n" ::: "memory"); }
__device__ __forceinline__ void cp_wait0()  { asm volatile("cp.async.wait_group 0;\n" ::: "memory"); }

__device__ __forceinline__ float ex2f(float x) {
    float r; asm("ex2.approx.ftz.f32 %0, %1;" : "=f"(r) : "f"(x)); return r;
}

// =================================================================
// SGEMM: C[8192,512] = X[8192,512] @ W[512,512] + bias  (unchanged, at FFMA roofline)
// mode 0: out[(h*8+b)][c][s]   mode 1: out[(h*8+b)][s][c]   mode 2: out[m][n]
// =================================================================
__global__ void __launch_bounds__(256) sgemm512(
    const float* __restrict__ X, const float* __restrict__ W,
    const float* __restrict__ bias, float* __restrict__ out, int mode)
{
    __shared__ float As[16][68];
    __shared__ float Bs[16][64];

    const int tid = threadIdx.x;
    const int tx = tid & 15, ty = tid >> 4;
    const int bm = blockIdx.y * 64, bn = blockIdx.x * 64;

    const int am = tid >> 2, ak = (tid & 3) << 2;
    const int wk = tid >> 4, wn = (tid & 15) << 2;

    float acc[4][4] = {};

    for (int k0 = 0; k0 < 512; k0 += 16) {
        float4 xa = *(const float4*)&X[(bm + am) * 512 + k0 + ak];
        float4 wb = *(const float4*)&W[(k0 + wk) * 512 + bn + wn];
        __syncthreads();
        As[ak + 0][am] = xa.x; As[ak + 1][am] = xa.y;
        As[ak + 2][am] = xa.z; As[ak + 3][am] = xa.w;
        *(float4*)&Bs[wk][wn] = wb;
        __syncthreads();
#pragma unroll
        for (int kk = 0; kk < 16; kk++) {
            const float4 a4 = *(const float4*)&As[kk][ty * 4];
            const float4 b4 = *(const float4*)&Bs[kk][tx * 4];
            const float a[4] = {a4.x, a4.y, a4.z, a4.w};
            const float b[4] = {b4.x, b4.y, b4.z, b4.w};
#pragma unroll
            for (int i = 0; i < 4; i++)
#pragma unroll
                for (int j = 0; j < 4; j++)
                    acc[i][j] = fmaf(a[i], b[j], acc[i][j]);
        }
    }

    const float4 bb4 = *(const float4*)(bias + bn + tx * 4);
    const float bb[4] = {bb4.x, bb4.y, bb4.z, bb4.w};
    const int m0 = bm + ty * 4;
    const int n0 = bn + tx * 4;

    if (mode == 2) {
#pragma unroll
        for (int i = 0; i < 4; i++) {
            float4 o = make_float4(acc[i][0] + bb[0], acc[i][1] + bb[1],
                                   acc[i][2] + bb[2], acc[i][3] + bb[3]);
            *(float4*)(out + (m0 + i) * 512 + n0) = o;
        }
    } else if (mode == 1) {  // V: [(h*8+b)][s][c]
        const int h = n0 >> 6, c = n0 & 63;
        const int b_ = m0 >> 10, s = m0 & 1023;
        float* base = out + ((h * 8 + b_) * SEQ + s) * DK + c;
#pragma unroll
        for (int i = 0; i < 4; i++) {
            float4 o = make_float4(acc[i][0] + bb[0], acc[i][1] + bb[1],
                                   acc[i][2] + bb[2], acc[i][3] + bb[3]);
            *(float4*)(base + i * DK) = o;
        }
    } else {                 // Q/K transposed: [(h*8+b)][c][s]
        const int h = n0 >> 6;
        const int b_ = m0 >> 10, s = m0 & 1023;
        float* base = out + (h * 8 + b_) * DK * SEQ + s;
#pragma unroll
        for (int j = 0; j < 4; j++) {
            const int c = (n0 & 63) + j;
            float4 o = make_float4(acc[0][j] + bb[j], acc[1][j] + bb[j],
                                   acc[2][j] + bb[j], acc[3][j] + bb[j]);
            *(float4*)(base + c * SEQ) = o;
        }
    }
}

// =================================================================
// Fused attention, 512 threads. Warp tiles keep 4 rows/warp (Q/score
// broadcasts amortized) by splitting keys/cols across warp pairs.
// One CTA = 32 queries of one n = h*8+b.
// =================================================================
#define KVBUF 8704                                     /* floats per buffer */
#define ATTN_SMEM_BYTES ((2048 + 32768 + 2*KVBUF) * 4) /* 208896 */

__device__ __forceinline__ void load_k_chunk(float* buf, const float* gK, int kc, int tid) {
#pragma unroll
    for (int j = 0; j < 4; j++) {                     // 2048 float4 / 512 thr
        int f = tid + 512 * j;
        int c = f >> 5;
        int kk = (f & 31) << 2;
        cp16(buf + c * 128 + kk, gK + c * SEQ + kc * 128 + kk);
    }
}
__device__ __forceinline__ void load_v_chunk(float* buf, const float* gV, int kc, int tid) {
#pragma unroll
    for (int j = 0; j < 4; j++) {
        int f = tid + 512 * j;
        int key = f >> 4;
        int c4 = (f & 15) << 2;
        cp16(buf + key * 68 + c4, gV + (kc * 128 + key) * DK + c4);
    }
}

__global__ void __launch_bounds__(512, 1) attn_kernel(const int* __restrict__ randidx, int n_rand)
{
    extern __shared__ float sm[];
    float* sQt  = sm;                    // [64][32]
    float* sS   = sm + 2048;             // [32][1024]
    float* sKV0 = sm + 2048 + 32768;
    float* sKV1 = sKV0 + KVBUF;
    __shared__ unsigned sRand[32];

    const int tid  = threadIdx.x;
    const int lane = tid & 31;
    const int warp = tid >> 5;           // 0..15
    const int qb = blockIdx.x;           // 0..31
    const int n  = blockIdx.y;           // h*8 + b

    const float* gQ = g_Qt + n * (DK * SEQ);
    const float* gK = g_Kt + n * (DK * SEQ);
    const float* gV = g_V  + n * (SEQ * DK);

    load_k_chunk(sKV0, gK, 0, tid);      // kick off K chunk 0
    cp_commit();

    if (tid < 32) sRand[tid] = 0u;
    {   // Q tile (pre-scaled by 1/sqrt(64)): 512 float4, one per thread
        int c = tid >> 3, s4 = (tid & 7) << 2;
        float4 v = *(const float4*)(gQ + c * SEQ + qb * 32 + s4);
        v.x *= 0.125f; v.y *= 0.125f; v.z *= 0.125f; v.w *= 0.125f;
        *(float4*)(sQt + c * 32 + s4) = v;
    }
    __syncthreads();
    if (tid < n_rand) {
        int v = randidx[tid] & (SEQ - 1);
        atomicOr(&sRand[v >> 5], 1u << (v & 31));
    }

    // ------- scores: warp = 4 rows x 64 keys (key half per warp pair) -------
    {
        const int r0 = (warp & 7) * 4;             // 8 row-groups of 4
        const int kh = (warp >> 3) * 64;           // key half: 0 / 64
        const int key0 = kh + lane * 2;
        const float* qp = sQt + r0;
        for (int kc = 0; kc < 8; kc++) {
            if (kc < 7) {
                load_k_chunk((kc & 1) ? sKV0 : sKV1, gK, kc + 1, tid);
                cp_commit();
                cp_wait1();
            } else {
                cp_wait0();
            }
            __syncthreads();
            const float* kp = ((kc & 1) ? sKV1 : sKV0) + key0;
            float a00=0.f,a01=0.f,a10=0.f,a11=0.f,a20=0.f,a21=0.f,a30=0.f,a31=0.f;
#pragma unroll 16
            for (int c = 0; c < 64; c++) {
                const float4 q  = *(const float4*)(qp + c * 32);   // broadcast
                const float2 k2 = *(const float2*)(kp + c * 128);
                a00 = fmaf(q.x, k2.x, a00); a01 = fmaf(q.x, k2.y, a01);
                a10 = fmaf(q.y, k2.x, a10); a11 = fmaf(q.y, k2.y, a11);
                a20 = fmaf(q.z, k2.x, a20); a21 = fmaf(q.z, k2.y, a21);
                a30 = fmaf(q.w, k2.x, a31 == a31 ? a30 : a30); a31 = fmaf(q.w, k2.y, a31);
            }
            float* sp = sS + r0 * 1024 + kc * 128 + key0;
            *(float2*)(sp)          = make_float2(a00, a01);
            *(float2*)(sp + 1024)   = make_float2(a10, a11);
            *(float2*)(sp + 2048)   = make_float2(a20, a21);
            *(float2*)(sp + 3072)   = make_float2(a30, a31);
            __syncthreads();
        }
    }

    load_v_chunk(sKV0, gV, 0, tid);      // prefetch V chunk 0 (overlaps topk)
    cp_commit();

    // ---- exp + exact top-51 (early-exit radix) + rand-mask + renorm ----
    {
#pragma unroll 1
        for (int rr = 0; rr < 2; rr++) {
            const int r = warp * 2 + rr;
            float* row = sS + r * 1024;
            float e[32];
            float m = -3.0e38f;
#pragma unroll
            for (int i = 0; i < 32; i++) { e[i] = row[lane + 32 * i]; m = fmaxf(m, e[i]); }
#pragma unroll
            for (int off = 16; off; off >>= 1) m = fmaxf(m, __shfl_xor_sync(0xFFFFFFFFu, m, off));
#pragma unroll
            for (int i = 0; i < 32; i++) e[i] = ex2f((e[i] - m) * 1.4426950408889634f);

            // exact 51st-largest threshold; stop as soon as count == TOPK
            unsigned prefix = 0u;
#pragma unroll 1
            for (int bit = 29; bit >= 0; bit--) {
                const unsigned cand = prefix | (1u << bit);
                int c = 0;
#pragma unroll
                for (int i = 0; i < 32; i++) c += (__float_as_uint(e[i]) >= cand) ? 1 : 0;
                c = __reduce_add_sync(0xFFFFFFFFu, c);
                if (c >= TOPK) {
                    prefix = cand;
                    if (c == TOPK) break;   // exact set resolved
                }
            }

            float s = 0.0f;
#pragma unroll
            for (int i = 0; i < 32; i++) {
                bool sel = (__float_as_uint(e[i]) >= prefix) || ((sRand[i] >> lane) & 1u);
                e[i] = sel ? e[i] * SCALE : e[i];
                s += e[i];
            }
#pragma unroll
            for (int off = 16; off; off >>= 1) s += __shfl_xor_sync(0xFFFFFFFFu, s, off);
            const float inv = 1.0f / s;
#pragma unroll
            for (int i = 0; i < 32; i++) row[lane + 32 * i] = e[i] * inv;
        }
    }

    // ------- AV: warp = 4 rows x 32 cols (col half per warp pair) -------
    {
        const int r0 = (warp & 7) * 4;
        const int c0 = (warp >> 3) * 32 + lane;    // one column per lane
        float acc0 = 0.f, acc1 = 0.f, acc2 = 0.f, acc3 = 0.f;
        const float* s0 = sS + r0 * 1024;
        for (int kc = 0; kc < 8; kc++) {
            if (kc < 7) {
                load_v_chunk((kc & 1) ? sKV0 : sKV1, gV, kc + 1, tid);
                cp_commit();
                cp_wait1();
            } else {
                cp_wait0();
            }
            __syncthreads();
            const float* Vb = ((kc & 1) ? sKV1 : sKV0) + c0;
            const int o = kc * 128;
#pragma unroll 8
            for (int kk = 0; kk < 128; kk += 4) {
                const float4 t0 = *(const float4*)(s0 + o + kk);           // bcast
                const float4 t1 = *(const float4*)(s0 + 1024 + o + kk);
                const float4 t2 = *(const float4*)(s0 + 2048 + o + kk);
                const float4 t3 = *(const float4*)(s0 + 3072 + o + kk);
                const float a0[4] = {t0.x, t0.y, t0.z, t0.w};
                const float a1[4] = {t1.x, t1.y, t1.z, t1.w};
                const float a2[4] = {t2.x, t2.y, t2.z, t2.w};
                const float a3[4] = {t3.x, t3.y, t3.z, t3.w};
#pragma unroll
                for (int t = 0; t < 4; t++) {
                    const float v = Vb[(kk + t) * 68];
                    acc0 = fmaf(a0[t], v, acc0);
                    acc1 = fmaf(a1[t], v, acc1);
                    acc2 = fmaf(a2[t], v, acc2);
                    acc3 = fmaf(a3[t], v, acc3);
                }
            }
            __syncthreads();
        }
        // write to g_attn[b][s][h*64+c]
        const int h = n >> 3, b_ = n & 7;
        const int s = qb * 32 + r0;
        float* ob = g_attn + (b_ * SEQ + s) * HID + h * 64 + c0;
        ob[0]       = acc0;
        ob[HID]     = acc1;
        ob[2 * HID] = acc2;
        ob[3 * HID] = acc3;
    }
}

// =================================================================
extern "C" void kernel_launch(void* const* d_in, const int* in_sizes, int n_in,
                              void* d_out, int out_size) {
    const float* Qx  = (const float*)d_in[0];
    const float* KVx = (const float*)d_in[1];
    const float* Wq  = (const float*)d_in[2];
    const float* bq  = (const float*)d_in[3];
    const float* Wk  = (const float*)d_in[4];
    const float* bk  = (const float*)d_in[5];
    const float* Wv  = (const float*)d_in[6];
    const float* bv  = (const float*)d_in[7];
    const float* Wo  = (const float*)d_in[8];
    const float* bo  = (const float*)d_in[9];
    const int* ridx  = (const int*)d_in[10];
    const int n_rand = in_sizes[10];
    float* out = (float*)d_out;

    float *pQt, *pKt, *pV, *pA;
    cudaGetSymbolAddress((void**)&pQt, g_Qt);
    cudaGetSymbolAddress((void**)&pKt, g_Kt);
    cudaGetSymbolAddress((void**)&pV,  g_V);
    cudaGetSymbolAddress((void**)&pA,  g_attn);

    cudaFuncSetAttribute(attn_kernel, cudaFuncAttributeMaxDynamicSharedMemorySize, ATTN_SMEM_BYTES);

    dim3 gg(8, 128);   // N tiles (512/64), M tiles (8192/64)
    sgemm512<<<gg, 256>>>(Qx,  Wq, bq, pQt, 0);
    sgemm512<<<gg, 256>>>(KVx, Wk, bk, pKt, 0);
    sgemm512<<<gg, 256>>>(KVx, Wv, bv, pV,  1);
    attn_kernel<<<dim3(32, 64), 512, ATTN_SMEM_BYTES>>>(ridx, n_rand);
    sgemm512<<<gg, 256>>>(pA, Wo, bo, out, 2);
}

// round 11
// speedup vs baseline: 1.2005x; 1.0441x over previous
#include <cuda_runtime.h>
#include <cstdint>

#define HEADS 8
#define BATCH 8
#define SEQ   1024
#define HID   512
#define DK    64
#define NH    (HEADS*BATCH)   /* 64 */
#define TOPK  51
#define SCALE 1.2f

#define SSTRIDE 1025          /* sS row stride: odd => conflict-free row access */

// ---------------- device scratch (allocation-free) ----------------
__device__ float g_Qt[(size_t)NH * DK * SEQ];      // [n][c][s]
__device__ float g_Kt[(size_t)NH * DK * SEQ];      // [n][c][s]
__device__ float g_V [(size_t)NH * SEQ * DK];      // [n][s][c]
__device__ float g_attn[(size_t)BATCH * SEQ * HID];// [b][s][h*64+c]

// ---------------- cp.async helpers ----------------
__device__ __forceinline__ void cp16(float* dst, const float* src) {
    unsigned u = (unsigned)__cvta_generic_to_shared(dst);
    asm volatile("cp.async.cg.shared.global [%0], [%1], 16;\n" :: "r"(u), "l"(src));
}
__device__ __forceinline__ void cp_commit() { asm volatile("cp.async.commit_group;\n" ::: "memory"); }
__device__ __forceinline__ void cp_wait1()  { asm volatile("cp.async.wait_group 1;\n" ::: "memory"); }
__device__ __forceinline__ void cp_wait0()  { asm volatile("cp.async.wait_group 0;\n" ::: "memory"); }

__device__ __forceinline__ float ex2f(float x) {
    float r; asm("ex2.approx.ftz.f32 %0, %1;" : "=f"(r) : "f"(x)); return r;
}

// =================================================================
// SGEMM: C[8192,512] = X[8192,512] @ W[512,512] + bias (at FFMA roofline)
// mode 0: out[(h*8+b)][c][s]   mode 1: out[(h*8+b)][s][c]   mode 2: out[m][n]
// =================================================================
__global__ void __launch_bounds__(256) sgemm512(
    const float* __restrict__ X, const float* __restrict__ W,
    const float* __restrict__ bias, float* __restrict__ out, int mode)
{
    __shared__ float As[16][68];
    __shared__ float Bs[16][64];

    const int tid = threadIdx.x;
    const int tx = tid & 15, ty = tid >> 4;
    const int bm = blockIdx.y * 64, bn = blockIdx.x * 64;

    const int am = tid >> 2, ak = (tid & 3) << 2;
    const int wk = tid >> 4, wn = (tid & 15) << 2;

    float acc[4][4] = {};

    for (int k0 = 0; k0 < 512; k0 += 16) {
        float4 xa = *(const float4*)&X[(bm + am) * 512 + k0 + ak];
        float4 wb = *(const float4*)&W[(k0 + wk) * 512 + bn + wn];
        __syncthreads();
        As[ak + 0][am] = xa.x; As[ak + 1][am] = xa.y;
        As[ak + 2][am] = xa.z; As[ak + 3][am] = xa.w;
        *(float4*)&Bs[wk][wn] = wb;
        __syncthreads();
#pragma unroll
        for (int kk = 0; kk < 16; kk++) {
            const float4 a4 = *(const float4*)&As[kk][ty * 4];
            const float4 b4 = *(const float4*)&Bs[kk][tx * 4];
            const float a[4] = {a4.x, a4.y, a4.z, a4.w};
            const float b[4] = {b4.x, b4.y, b4.z, b4.w};
#pragma unroll
            for (int i = 0; i < 4; i++)
#pragma unroll
                for (int j = 0; j < 4; j++)
                    acc[i][j] = fmaf(a[i], b[j], acc[i][j]);
        }
    }

    const float4 bb4 = *(const float4*)(bias + bn + tx * 4);
    const float bb[4] = {bb4.x, bb4.y, bb4.z, bb4.w};
    const int m0 = bm + ty * 4;
    const int n0 = bn + tx * 4;

    if (mode == 2) {
#pragma unroll
        for (int i = 0; i < 4; i++) {
            float4 o = make_float4(acc[i][0] + bb[0], acc[i][1] + bb[1],
                                   acc[i][2] + bb[2], acc[i][3] + bb[3]);
            *(float4*)(out + (m0 + i) * 512 + n0) = o;
        }
    } else if (mode == 1) {  // V: [(h*8+b)][s][c]
        const int h = n0 >> 6, c = n0 & 63;
        const int b_ = m0 >> 10, s = m0 & 1023;
        float* base = out + ((h * 8 + b_) * SEQ + s) * DK + c;
#pragma unroll
        for (int i = 0; i < 4; i++) {
            float4 o = make_float4(acc[i][0] + bb[0], acc[i][1] + bb[1],
                                   acc[i][2] + bb[2], acc[i][3] + bb[3]);
            *(float4*)(base + i * DK) = o;
        }
    } else {                 // Q/K transposed: [(h*8+b)][c][s]
        const int h = n0 >> 6;
        const int b_ = m0 >> 10, s = m0 & 1023;
        float* base = out + (h * 8 + b_) * DK * SEQ + s;
#pragma unroll
        for (int j = 0; j < 4; j++) {
            const int c = (n0 & 63) + j;
            float4 o = make_float4(acc[0][j] + bb[j], acc[1][j] + bb[j],
                                   acc[2][j] + bb[j], acc[3][j] + bb[j]);
            *(float4*)(base + c * SEQ) = o;
        }
    }
}

// =================================================================
// Fused attention, 512 threads, broadcast-maximizing lane maps.
// One CTA = 32 queries of one n = h*8+b.
// SMEM: sQt[64][32] | sS[32][1025] | 2x KV buffer.
// =================================================================
#define KVBUF 8704                                           /* floats */
#define SQ_FLOATS 2048
#define SS_FLOATS (32 * SSTRIDE)                             /* 32800 */
#define ATTN_SMEM_BYTES ((SQ_FLOATS + SS_FLOATS + 2*KVBUF) * 4) /* 209024 */

__device__ __forceinline__ void load_k_chunk(float* buf, const float* gK, int kc, int tid) {
#pragma unroll
    for (int j = 0; j < 4; j++) {                     // 2048 float4 / 512 thr
        int f = tid + 512 * j;
        int c = f >> 5;
        int kk = (f & 31) << 2;
        cp16(buf + c * 128 + kk, gK + c * SEQ + kc * 128 + kk);
    }
}
__device__ __forceinline__ void load_v_chunk(float* buf, const float* gV, int kc, int tid) {
#pragma unroll
    for (int j = 0; j < 4; j++) {
        int f = tid + 512 * j;
        int key = f >> 4;
        int c4 = (f & 15) << 2;
        cp16(buf + key * 68 + c4, gV + (kc * 128 + key) * DK + c4);
    }
}

__global__ void __launch_bounds__(512, 1) attn_kernel(const int* __restrict__ randidx, int n_rand)
{
    extern __shared__ float sm[];
    float* sQt  = sm;                        // [64][32]
    float* sS   = sm + SQ_FLOATS;            // [32][1025]
    float* sKV0 = sm + SQ_FLOATS + SS_FLOATS;
    float* sKV1 = sKV0 + KVBUF;
    __shared__ unsigned sRand[32];

    const int tid  = threadIdx.x;
    const int lane = tid & 31;
    const int warp = tid >> 5;               // 0..15
    const int qb = blockIdx.x;               // 0..31
    const int n  = blockIdx.y;               // h*8 + b

    const float* gQ = g_Qt + n * (DK * SEQ);
    const float* gK = g_Kt + n * (DK * SEQ);
    const float* gV = g_V  + n * (SEQ * DK);

    load_k_chunk(sKV0, gK, 0, tid);          // kick off K chunk 0
    cp_commit();

    if (tid < 32) sRand[tid] = 0u;
    {   // Q tile (pre-scaled by 1/sqrt(64)): 512 float4, one per thread
        int c = tid >> 3, s4 = (tid & 7) << 2;
        float4 v = *(const float4*)(gQ + c * SEQ + qb * 32 + s4);
        v.x *= 0.125f; v.y *= 0.125f; v.z *= 0.125f; v.w *= 0.125f;
        *(float4*)(sQt + c * 32 + s4) = v;
    }
    __syncthreads();
    if (tid < n_rand) {
        int v = randidx[tid] & (SEQ - 1);
        atomicOr(&sRand[v >> 5], 1u << (v & 31));
    }

    // ---- scores: thread = 4 rows x 2 keys (rowg=tid&7 for warp dedup) ----
    {
        const int rowg = tid & 7;            // Q float4: 8 distinct/warp
        const int keyg = tid >> 3;           // K float2: 4 distinct/warp
        const int r0 = rowg * 4;
        const int key0 = keyg * 2;
        const float* qp = sQt + r0;
        for (int kc = 0; kc < 8; kc++) {
            if (kc < 7) {
                load_k_chunk((kc & 1) ? sKV0 : sKV1, gK, kc + 1, tid);
                cp_commit();
                cp_wait1();
            } else {
                cp_wait0();
            }
            __syncthreads();
            const float* kp = ((kc & 1) ? sKV1 : sKV0) + key0;
            float a00=0.f,a01=0.f,a10=0.f,a11=0.f,a20=0.f,a21=0.f,a30=0.f,a31=0.f;
#pragma unroll 16
            for (int c = 0; c < 64; c++) {
                const float4 q  = *(const float4*)(qp + c * 32);   // 8-way dedup
                const float2 k2 = *(const float2*)(kp + c * 128);  // 4-way dedup
                a00 = fmaf(q.x, k2.x, a00); a01 = fmaf(q.x, k2.y, a01);
                a10 = fmaf(q.y, k2.x, a10); a11 = fmaf(q.y, k2.y, a11);
                a20 = fmaf(q.z, k2.x, a20); a21 = fmaf(q.z, k2.y, a21);
                a30 = fmaf(q.w, k2.x, a30); a31 = fmaf(q.w, k2.y, a31);
            }
            float* sp = sS + r0 * SSTRIDE + kc * 128 + key0;
            sp[0] = a00;              sp[1] = a01;
            sp[SSTRIDE] = a10;        sp[SSTRIDE + 1] = a11;
            sp[2 * SSTRIDE] = a20;    sp[2 * SSTRIDE + 1] = a21;
            sp[3 * SSTRIDE] = a30;    sp[3 * SSTRIDE + 1] = a31;
            __syncthreads();
        }
    }

    load_v_chunk(sKV0, gV, 0, tid);          // prefetch V chunk 0 (overlaps topk)
    cp_commit();

    // ---- exp + exact top-51 (early-exit radix) + rand-mask + renorm ----
    {
#pragma unroll 1
        for (int rr = 0; rr < 2; rr++) {
            const int r = warp * 2 + rr;
            float* row = sS + r * SSTRIDE;
            float e[32];
            float m = -3.0e38f;
#pragma unroll
            for (int i = 0; i < 32; i++) { e[i] = row[lane + 32 * i]; m = fmaxf(m, e[i]); }
#pragma unroll
            for (int off = 16; off; off >>= 1) m = fmaxf(m, __shfl_xor_sync(0xFFFFFFFFu, m, off));
#pragma unroll
            for (int i = 0; i < 32; i++) e[i] = ex2f((e[i] - m) * 1.4426950408889634f);

            // exact 51st-largest threshold; stop as soon as count == TOPK
            unsigned prefix = 0u;
#pragma unroll 1
            for (int bit = 29; bit >= 0; bit--) {
                const unsigned cand = prefix | (1u << bit);
                int c = 0;
#pragma unroll
                for (int i = 0; i < 32; i++) c += (__float_as_uint(e[i]) >= cand) ? 1 : 0;
                c = __reduce_add_sync(0xFFFFFFFFu, c);
                if (c >= TOPK) {
                    prefix = cand;
                    if (c == TOPK) break;   // exact set resolved
                }
            }

            float s = 0.0f;
#pragma unroll
            for (int i = 0; i < 32; i++) {
                bool sel = (__float_as_uint(e[i]) >= prefix) || ((sRand[i] >> lane) & 1u);
                e[i] = sel ? e[i] * SCALE : e[i];
                s += e[i];
            }
#pragma unroll
            for (int off = 16; off; off >>= 1) s += __shfl_xor_sync(0xFFFFFFFFu, s, off);
            const float inv = 1.0f / s;
#pragma unroll
            for (int i = 0; i < 32; i++) row[lane + 32 * i] = e[i] * inv;
        }
    }

    // ---- AV: thread = 4 rows x 4 cols, 4-way k-split (kq), smem reduce ----
    {
        const int t128 = tid & 127;
        const int rowg = t128 & 7;           // S scalars: 8 distinct rows/warp
        const int colg = (t128 >> 3) & 15;   // V float4: 4 distinct/warp
        const int kq   = tid >> 7;           // 0..3: k-quarter of each chunk
        const int r0 = rowg * 4;
        const int c0 = colg * 4;
        const int kb = kq * 32;
        float acc[4][4] = {};
        for (int kc = 0; kc < 8; kc++) {
            if (kc < 7) {
                load_v_chunk((kc & 1) ? sKV0 : sKV1, gV, kc + 1, tid);
                cp_commit();
                cp_wait1();
            } else {
                cp_wait0();
            }
            __syncthreads();
            const float* Vb = ((kc & 1) ? sKV1 : sKV0) + c0;
            const float* Sb = sS + r0 * SSTRIDE + kc * 128;
#pragma unroll 4
            for (int k = kb; k < kb + 32; k++) {
                const float4 v4 = *(const float4*)(Vb + k * 68);
#pragma unroll
                for (int i = 0; i < 4; i++) {
                    const float s = Sb[i * SSTRIDE + k];
                    acc[i][0] = fmaf(s, v4.x, acc[i][0]);
                    acc[i][1] = fmaf(s, v4.y, acc[i][1]);
                    acc[i][2] = fmaf(s, v4.z, acc[i][2]);
                    acc[i][3] = fmaf(s, v4.w, acc[i][3]);
                }
            }
            __syncthreads();
        }

        // reduce the 4 kq-partials through sKV0 (free after last V chunk)
        float* scratch = sKV0;
        if (kq != 0) {
            float* dst = scratch + ((kq - 1) * 128 + t128) * 16;
#pragma unroll
            for (int i = 0; i < 4; i++)
                *(float4*)(dst + i * 4) = make_float4(acc[i][0], acc[i][1], acc[i][2], acc[i][3]);
        }
        __syncthreads();
        if (kq == 0) {
#pragma unroll
            for (int p = 0; p < 3; p++) {
                const float* src = scratch + (p * 128 + t128) * 16;
#pragma unroll
                for (int i = 0; i < 4; i++) {
                    const float4 t = *(const float4*)(src + i * 4);
                    acc[i][0] += t.x; acc[i][1] += t.y; acc[i][2] += t.z; acc[i][3] += t.w;
                }
            }
            // write to g_attn[b][s][h*64+c]
            const int h = n >> 3, b_ = n & 7;
            const int s = qb * 32 + r0;
            float* ob = g_attn + (b_ * SEQ + s) * HID + h * 64 + c0;
#pragma unroll
            for (int i = 0; i < 4; i++)
                *(float4*)(ob + i * HID) = make_float4(acc[i][0], acc[i][1], acc[i][2], acc[i][3]);
        }
    }
}

// =================================================================
extern "C" void kernel_launch(void* const* d_in, const int* in_sizes, int n_in,
                              void* d_out, int out_size) {
    const float* Qx  = (const float*)d_in[0];
    const float* KVx = (const float*)d_in[1];
    const float* Wq  = (const float*)d_in[2];
    const float* bq  = (const float*)d_in[3];
    const float* Wk  = (const float*)d_in[4];
    const float* bk  = (const float*)d_in[5];
    const float* Wv  = (const float*)d_in[6];
    const float* bv  = (const float*)d_in[7];
    const float* Wo  = (const float*)d_in[8];
    const float* bo  = (const float*)d_in[9];
    const int* ridx  = (const int*)d_in[10];
    const int n_rand = in_sizes[10];
    float* out = (float*)d_out;

    float *pQt, *pKt, *pV, *pA;
    cudaGetSymbolAddress((void**)&pQt, g_Qt);
    cudaGetSymbolAddress((void**)&pKt, g_Kt);
    cudaGetSymbolAddress((void**)&pV,  g_V);
    cudaGetSymbolAddress((void**)&pA,  g_attn);

    cudaFuncSetAttribute(attn_kernel, cudaFuncAttributeMaxDynamicSharedMemorySize, ATTN_SMEM_BYTES);

    dim3 gg(8, 128);   // N tiles (512/64), M tiles (8192/64)
    sgemm512<<<gg, 256>>>(Qx,  Wq, bq, pQt, 0);
    sgemm512<<<gg, 256>>>(KVx, Wk, bk, pKt, 0);
    sgemm512<<<gg, 256>>>(KVx, Wv, bv, pV,  1);
    attn_kernel<<<dim3(32, 64), 512, ATTN_SMEM_BYTES>>>(ridx, n_rand);
    sgemm512<<<gg, 256>>>(pA, Wo, bo, out, 2);
}